// round 5
// baseline (speedup 1.0000x reference)
#include <cuda_runtime.h>
#include <cstdint>

// SINDy library: out[row] = [1, z(32), z_i*z_j (528), z_a*z_b*z_c (5984), sin(z)(32)]
// 8192 rows x 6577 cols fp32. value(col) = z_or_1[a] * buf[k], k consecutive within
// each a-segment. R5: branchless 8-col groups (2x LDS.128 + 2x STG.128 + f32x2 muls),
// precomputed byte-offset tables, compute-then-fixup for segment boundaries.

#define NDIM     32
#define NPAIRS   528
#define NCOLS    6577
#define SBUF_PAD 600
#define NG_MAX   823
#define TB_PAD   1088          // NG_MAX + 256 prefetch pad, rounded
#define FIX_MAX  288

static constexpr int pair_index(int i, int j) {
    return i * NDIM - (i * (i - 1)) / 2 + (j - i);
}

struct ColTbl { unsigned short e[NCOLS]; };   // per column: k | (a<<10)

static constexpr ColTbl make_col_tbl() {
    ColTbl t{};
    for (int c = 0; c < 561; ++c)                       // 1, z, pairs: k=c, a=32 (=1.0)
        t.e[c] = (unsigned short)((unsigned)c | (32u << 10));
    {
        int col = 561;                                  // triples
        for (int a = 0; a < NDIM; ++a)
            for (int b = a; b < NDIM; ++b)
                for (int c = b; c < NDIM; ++c) {
                    unsigned k = 33u + (unsigned)pair_index(b, c);
                    t.e[col++] = (unsigned short)(k | ((unsigned)a << 10));
                }
    }
    for (int i = 0; i < NDIM; ++i)                      // sin: k = 561+i, a=32
        t.e[6545 + i] = (unsigned short)((unsigned)(561 + i) | (32u << 10));
    return t;
}
__device__ constexpr ColTbl G_COL = make_col_tbl();

// Per phase ph (= (-row)&3): 8-col groups starting at c0 = ph + 8*g.
// Entry: low16 = byte offset into s_copy (copy P chosen so LDS.128 is 16B-aligned),
//        high16 = a*8 (byte offset into float2 s_mul2).
struct Tbl8 {
    unsigned e[4][TB_PAD];
    unsigned fix[4][FIX_MAX];   // (col<<16) | colentry16
    int      ng[4];
    int      nfix[4];
};

static constexpr Tbl8 make_tbl8() {
    ColTbl ct = make_col_tbl();
    Tbl8 t{};
    for (int ph = 0; ph < 4; ++ph) {
        int ng = (NCOLS - ph) / 8;
        t.ng[ph] = ng;
        int nf = 0;
        for (int g = 0; g < ng; ++g) {
            int c0 = ph + 8 * g;
            unsigned k0 = ct.e[c0] & 1023u;
            unsigned a0 = (unsigned)(ct.e[c0] >> 10);
            bool uniform = true;
            for (int j = 1; j < 8; ++j) {
                unsigned kj = ct.e[c0 + j] & 1023u;
                unsigned aj = (unsigned)(ct.e[c0 + j] >> 10);
                if (kj != k0 + (unsigned)j || aj != a0) { uniform = false; break; }
            }
            unsigned P   = (4u - (k0 & 3u)) & 3u;
            unsigned off = (P * SBUF_PAD + k0 + P) * 4u;
            t.e[ph][g] = off | ((a0 * 8u) << 16);
            if (!uniform) {
                for (int j = 0; j < 8; ++j)
                    t.fix[ph][nf++] =
                        ((unsigned)(c0 + j) << 16) | (unsigned)ct.e[c0 + j];
            }
        }
        for (int g = ng; g < TB_PAD; ++g) t.e[ph][g] = 0;  // prefetch pad (benign)
        t.nfix[ph] = nf;
    }
    return t;
}
__device__ constexpr Tbl8 G8 = make_tbl8();

struct PairTbl { unsigned short e[NPAIRS]; };
static constexpr PairTbl make_pair_tbl() {
    PairTbl t{};
    int p = 0;
    for (int i = 0; i < NDIM; ++i)
        for (int j = i; j < NDIM; ++j)
            t.e[p++] = (unsigned short)((unsigned)i | ((unsigned)j << 8));
    return t;
}
__device__ constexpr PairTbl G_PAIR = make_pair_tbl();

__device__ __forceinline__ void mul2(float& ox, float& oy,
                                     float ax, float ay, uint64_t b) {
    uint64_t a, r;
    asm("mov.b64 %0,{%1,%2};" : "=l"(a) : "f"(ax), "f"(ay));
    asm("mul.rn.f32x2 %0,%1,%2;" : "=l"(r) : "l"(a), "l"(b));
    asm("mov.b64 {%0,%1},%2;" : "=f"(ox), "=f"(oy) : "l"(r));
}

__global__ __launch_bounds__(256) void sindy_library_kernel(
    const float* __restrict__ z, float* __restrict__ out)
{
    // 4 shifted copies: s_copy[P][P + k] = buf[k]; reading 16B at (k0+P), P=(-k0)&3,
    // is 16B-aligned and conflict-free.
    __shared__ __align__(16) float s_copy[4][SBUF_PAD];
    __shared__ __align__(8)  float s_mul2[2 * (NDIM + 1)];  // duplicated (v,v) pairs
    __shared__ float s_mul[NDIM + 1];

    const int row = blockIdx.x;
    const int t   = threadIdx.x;

    if (t < NDIM) {
        float v = z[row * NDIM + t];
        float sv = __sinf(v);
        s_mul[t] = v;
        s_mul2[2 * t]     = v;
        s_mul2[2 * t + 1] = v;
        #pragma unroll
        for (int P = 0; P < 4; ++P) {
            s_copy[P][P + 1 + t]   = v;
            s_copy[P][P + 561 + t] = sv;
        }
    } else if (t == NDIM) {
        s_mul[NDIM] = 1.0f;
        s_mul2[2 * NDIM]     = 1.0f;
        s_mul2[2 * NDIM + 1] = 1.0f;
        #pragma unroll
        for (int P = 0; P < 4; ++P) s_copy[P][P] = 1.0f;
    }
    __syncthreads();

    // Pair products into all 4 shifted copies.
    #pragma unroll
    for (int p = t; p < NPAIRS; p += 256) {
        unsigned ij = (unsigned)G_PAIR.e[p];
        float v = s_mul[ij & 31u] * s_mul[(ij >> 8) & 31u];
        #pragma unroll
        for (int P = 0; P < 4; ++P) s_copy[P][P + 33 + p] = v;
    }
    __syncthreads();

    float* __restrict__ o = out + (size_t)row * NCOLS;
    const int ph = (4 - (row & 3)) & 3;

    // Head scalars (< 4 cols)
    if (t < ph) {
        unsigned e = (unsigned)G_COL.e[t];
        o[t] = s_mul[e >> 10] * s_copy[0][e & 1023u];
    }

    // Branchless uniform pass over ALL 8-col groups (boundary groups write
    // garbage; fixed up after the barrier).
    const int ng = G8.ng[ph];
    const unsigned* __restrict__ tb = &G8.e[ph][0];
    const char* __restrict__ sc = (const char*)&s_copy[0][0];
    const char* __restrict__ sm = (const char*)&s_mul2[0];

    unsigned e = __ldg(&tb[t]);
    for (int g = t; g < ng; g += 256) {
        unsigned en = __ldg(&tb[g + 256]);     // padded: always safe
        unsigned off = e & 0xFFFFu;
        float4 b0 = *(const float4*)(sc + off);
        float4 b1 = *(const float4*)(sc + off + 16);
        uint64_t zz = *(const uint64_t*)(sm + (e >> 16));
        float4 r0, r1;
        mul2(r0.x, r0.y, b0.x, b0.y, zz);
        mul2(r0.z, r0.w, b0.z, b0.w, zz);
        mul2(r1.x, r1.y, b1.x, b1.y, zz);
        mul2(r1.z, r1.w, b1.z, b1.w, zz);
        float* po = o + ph + 8 * g;
        *(float4*)po       = r0;
        *(float4*)(po + 4) = r1;
        e = en;
    }

    // Tail scalars (< 8 cols)
    {
        int c = ph + 8 * ng + t;
        if (c < NCOLS) {
            unsigned ee = (unsigned)G_COL.e[c];
            o[c] = s_mul[ee >> 10] * s_copy[0][ee & 1023u];
        }
    }

    __syncthreads();   // order fixup stores after the uniform-pass stores

    // Fixup pass: overwrite boundary-group columns with correct values.
    const int nfix = G8.nfix[ph];
    for (int i = t; i < nfix; i += 256) {
        unsigned f = __ldg(&G8.fix[ph][i]);
        int c = (int)(f >> 16);
        unsigned e16 = f & 0xFFFFu;
        o[c] = s_mul[e16 >> 10] * s_copy[0][e16 & 1023u];
    }
}

extern "C" void kernel_launch(void* const* d_in, const int* in_sizes, int n_in,
                              void* d_out, int out_size) {
    const float* z   = (const float*)d_in[0];
    float*       out = (float*)d_out;
    sindy_library_kernel<<<8192, 256>>>(z, out);
}

// round 7
// speedup vs baseline: 1.4659x; 1.4659x over previous
#include <cuda_runtime.h>
#include <cstdint>

// SINDy library: out[row] = [1, z(32), z_i*z_j (528), z_a*z_b*z_c (5984), sin(z)(32)]
// 8192 rows x 6577 cols fp32. value(col) = s_mul[a] * s_buf[k]; s_mul[32] = 1.0
// makes the non-triple regions use the SAME uniform path (multiply by 1).
// R7 = R6 with the pair-build bug fixed (528 pairs > 512 threads -> strided loop).

#define NDIM     32
#define NPAIRS   528
#define NCOLS    6577
#define SBUF_PAD 600
#define NTHREADS 512
#define TB_PAD   2176          // >= max ng (1644) + NTHREADS pad

static constexpr int pair_index(int i, int j) {
    return i * NDIM - (i * (i - 1)) / 2 + (j - i);
}

struct ColTbl { unsigned short e[NCOLS]; };   // per column: k | (a<<10)

static constexpr ColTbl make_col_tbl() {
    ColTbl t{};
    for (int c = 0; c < 561; ++c)                       // 1, z, pairs: k=c, a=32 (=1.0)
        t.e[c] = (unsigned short)((unsigned)c | (32u << 10));
    {
        int col = 561;                                  // triples
        for (int a = 0; a < NDIM; ++a)
            for (int b = a; b < NDIM; ++b)
                for (int c = b; c < NDIM; ++c) {
                    unsigned k = 33u + (unsigned)pair_index(b, c);
                    t.e[col++] = (unsigned short)(k | ((unsigned)a << 10));
                }
    }
    for (int i = 0; i < NDIM; ++i)                      // sin: k = 561+i, a=32
        t.e[6545 + i] = (unsigned short)((unsigned)(561 + i) | (32u << 10));
    return t;
}
__device__ constexpr ColTbl G_COL = make_col_tbl();

// Per phase ph = (-row)&3, per 4-col group g (c0 = ph + 4g):
//   uniform group: low16  = byte offset into s_copy (copy chosen for 16B alignment)
//                  bits[16..30) = a*4 (byte offset into s_mul; a=32 -> 1.0f)
//   boundary group: bit31 set (low16 = 0 -> safe dummy LDS).
struct Tbl4 {
    unsigned e[4][TB_PAD];
    int      ng[4];
};

static constexpr Tbl4 make_tbl4() {
    ColTbl ct = make_col_tbl();
    Tbl4 t{};
    for (int ph = 0; ph < 4; ++ph) {
        int ng = (NCOLS - ph) / 4;
        t.ng[ph] = ng;
        for (int g = 0; g < ng; ++g) {
            int c0 = ph + 4 * g;
            unsigned k0 = ct.e[c0] & 1023u;
            unsigned a0 = (unsigned)(ct.e[c0] >> 10);
            bool uniform = true;
            for (int j = 1; j < 4; ++j) {
                unsigned kj = ct.e[c0 + j] & 1023u;
                unsigned aj = (unsigned)(ct.e[c0 + j] >> 10);
                if (kj != k0 + (unsigned)j || aj != a0) { uniform = false; break; }
            }
            if (uniform) {
                unsigned P   = (4u - (k0 & 3u)) & 3u;
                unsigned off = (P * SBUF_PAD + k0 + P) * 4u;
                t.e[ph][g] = off | ((a0 * 4u) << 16);
            } else {
                t.e[ph][g] = 0x80000000u;
            }
        }
        for (int g = ng; g < TB_PAD; ++g) t.e[ph][g] = 0;  // prefetch pad (never consumed)
    }
    return t;
}
__device__ constexpr Tbl4 G4 = make_tbl4();

struct PairTbl { unsigned short e[NPAIRS]; };
static constexpr PairTbl make_pair_tbl() {
    PairTbl t{};
    int p = 0;
    for (int i = 0; i < NDIM; ++i)
        for (int j = i; j < NDIM; ++j)
            t.e[p++] = (unsigned short)((unsigned)i | ((unsigned)j << 8));
    return t;
}
__device__ constexpr PairTbl G_PAIR = make_pair_tbl();

__global__ __launch_bounds__(NTHREADS) void sindy_library_kernel(
    const float* __restrict__ z, float* __restrict__ out)
{
    // 4 shifted copies: s_copy[P][P + k] = buf[k]; LDS.128 at (k0+P), P=(-k0)&3,
    // is 16B-aligned and conflict-free.
    __shared__ __align__(16) float s_copy[4][SBUF_PAD];
    __shared__ float s_mul[NDIM + 1];   // z..., then 1.0f at [32]

    const int row = blockIdx.x;
    const int t   = threadIdx.x;

    if (t < NDIM) {
        float v = z[row * NDIM + t];
        float sv = __sinf(v);
        s_mul[t] = v;
        #pragma unroll
        for (int P = 0; P < 4; ++P) {
            s_copy[P][P + 1 + t]   = v;
            s_copy[P][P + 561 + t] = sv;
        }
    } else if (t == NDIM) {
        s_mul[NDIM] = 1.0f;
        #pragma unroll
        for (int P = 0; P < 4; ++P) s_copy[P][P] = 1.0f;
    }
    __syncthreads();

    // 528 pair products into all 4 shifted copies.
    // NPAIRS (528) > NTHREADS (512): strided loop, NOT a single if!
    for (int p = t; p < NPAIRS; p += NTHREADS) {
        unsigned ij = (unsigned)G_PAIR.e[p];
        float v = s_mul[ij & 31u] * s_mul[(ij >> 8) & 31u];
        #pragma unroll
        for (int P = 0; P < 4; ++P) s_copy[P][P + 33 + p] = v;
    }
    __syncthreads();

    float* __restrict__ o = out + (size_t)row * NCOLS;
    const int ph = (4 - (row & 3)) & 3;

    // Head scalars (< 4 cols)
    if (t < ph) {
        unsigned e = (unsigned)G_COL.e[t];
        o[t] = s_mul[e >> 10] * s_copy[0][e & 1023u];
    }

    const int ng = G4.ng[ph];
    const unsigned* __restrict__ tb = &G4.e[ph][0];
    const char* __restrict__ sc = (const char*)&s_copy[0][0];
    const char* __restrict__ sm = (const char*)&s_mul[0];

    unsigned e = __ldg(&tb[t]);                 // prefetch first entry
    for (int g = t; g < ng; g += NTHREADS) {
        unsigned en = __ldg(&tb[g + NTHREADS]); // padded: always in-bounds

        // Uniform path (runs for every group; boundary entries read safe dummies).
        float4 b  = *(const float4*)(sc + (e & 0xFFFFu));
        float  za = *(const float*)(sm + ((e >> 16) & 0x3FFFu));
        float4 r  = make_float4(za * b.x, za * b.y, za * b.z, za * b.w);

        if ((int)e < 0) {                       // rare boundary group (~2%)
            const int c0 = ph + 4 * g;
            unsigned e0 = (unsigned)G_COL.e[c0];
            unsigned e1 = (unsigned)G_COL.e[c0 + 1];
            unsigned e2 = (unsigned)G_COL.e[c0 + 2];
            unsigned e3 = (unsigned)G_COL.e[c0 + 3];
            r.x = s_mul[e0 >> 10] * s_copy[0][e0 & 1023u];
            r.y = s_mul[e1 >> 10] * s_copy[0][e1 & 1023u];
            r.z = s_mul[e2 >> 10] * s_copy[0][e2 & 1023u];
            r.w = s_mul[e3 >> 10] * s_copy[0][e3 & 1023u];
        }

        __stcs((float4*)(o + ph + 4 * g), r);   // streaming store; single store point
        e = en;
    }

    // Tail scalars (< 4 cols)
    {
        int c = ph + 4 * ng + t;
        if (c < NCOLS) {
            unsigned ee = (unsigned)G_COL.e[c];
            o[c] = s_mul[ee >> 10] * s_copy[0][ee & 1023u];
        }
    }
}

extern "C" void kernel_launch(void* const* d_in, const int* in_sizes, int n_in,
                              void* d_out, int out_size) {
    const float* z   = (const float*)d_in[0];
    float*       out = (float*)d_out;
    sindy_library_kernel<<<8192, NTHREADS>>>(z, out);
}